// round 1
// baseline (speedup 1.0000x reference)
#include <cuda_runtime.h>

// Problem constants (fixed by the reference setup)
#define DE   200          // entity / output dim
#define DR   200          // relation dim
#define DIN  400          // DE + DR
#define NB   4            // num bases

// scratch (static device globals — no allocation)
#define MAXM 65536
__device__ int g_count;
__device__ int g_edges[MAXM];

// K0: zero output accumulator + reset match counter (must run every call:
// kernel_launch is replayed from a captured graph and must be deterministic).
__global__ void k_init(float* __restrict__ out) {
    int t = blockIdx.x * blockDim.x + threadIdx.x;
    if (t < DE) out[t] = 0.0f;
    if (t == 0) g_count = 0;
}

// K1: scan all edges, collect indices whose destination == unseen_index.
__global__ void k_scan(const int* __restrict__ edge_dst,
                       const int* __restrict__ u_ptr, int E) {
    int e = blockIdx.x * blockDim.x + threadIdx.x;
    if (e >= E) return;
    int u = *u_ptr;   // broadcast load, L1/L2 cached
    if (edge_dst[e] == u) {
        int p = atomicAdd(&g_count, 1);
        if (p < MAXM) g_edges[p] = e;
    }
}

// K2: one block per matched edge (grid-strided over the collected list).
// msg[o] = sum_i xj[i] * ( sum_b att[t,b] * basis[b,i,o] )
// xj = concat(entity[node_id[edge_src[e]]], relation[rel_index[e]])
__global__ void k_msg(const float* __restrict__ ent,
                      const float* __restrict__ relemb,
                      const float* __restrict__ basis,
                      const float* __restrict__ att,
                      const int*   __restrict__ node_id,
                      const int*   __restrict__ edge_src,
                      const int*   __restrict__ edge_type,
                      const int*   __restrict__ rel_index,
                      float* __restrict__ out) {
    __shared__ float xj[DIN];
    __shared__ float a[NB];
    int tid = threadIdx.x;
    int cnt = g_count;
    int mmax = cnt < MAXM ? cnt : MAXM;

    for (int m = blockIdx.x; m < mmax; m += gridDim.x) {
        int e   = g_edges[m];
        int nid = node_id[edge_src[e]];
        int ri  = rel_index[e];
        int ty  = edge_type[e];

        if (tid < NB) a[tid] = att[ty * NB + tid];
        for (int i = tid; i < DE; i += blockDim.x) xj[i]      = ent[(long)nid * DE + i];
        for (int i = tid; i < DR; i += blockDim.x) xj[DE + i] = relemb[ri * DR + i];
        __syncthreads();

        if (tid < DE) {
            float a0 = a[0], a1 = a[1], a2 = a[2], a3 = a[3];
            float acc = 0.0f;
            #pragma unroll 4
            for (int i = 0; i < DIN; i++) {
                float w = a0 * basis[(0 * DIN + i) * DE + tid]
                        + a1 * basis[(1 * DIN + i) * DE + tid]
                        + a2 * basis[(2 * DIN + i) * DE + tid]
                        + a3 * basis[(3 * DIN + i) * DE + tid];
                acc += xj[i] * w;
            }
            atomicAdd(&out[tid], acc);
        }
        __syncthreads();
    }
}

// K3: mean normalization by the true match count (even if list was clamped).
__global__ void k_div(float* __restrict__ out) {
    int t = threadIdx.x;
    if (t < DE) {
        float c = (float)g_count;
        out[t] = out[t] / fmaxf(c, 1.0f);
    }
}

extern "C" void kernel_launch(void* const* d_in, const int* in_sizes, int n_in,
                              void* d_out, int out_size) {
    const float* ent    = (const float*)d_in[0];  // [100000, 200]
    const float* relemb = (const float*)d_in[1];  // [200, 200]
    const float* basis  = (const float*)d_in[2];  // [4, 400, 200]
    const float* att    = (const float*)d_in[3];  // [400, 4]
    const int* node_id  = (const int*)d_in[4];    // [50000]
    const int* edge_src = (const int*)d_in[5];    // [400000]
    const int* edge_dst = (const int*)d_in[6];    // [400000]
    const int* edge_typ = (const int*)d_in[7];    // [400000]
    const int* rel_idx  = (const int*)d_in[8];    // [400000]
    const int* u_ptr    = (const int*)d_in[9];    // scalar
    float* out = (float*)d_out;                   // [200]

    int E = in_sizes[6];

    k_init<<<1, 256>>>(out);
    k_scan<<<(E + 255) / 256, 256>>>(edge_dst, u_ptr, E);
    k_msg<<<64, 256>>>(ent, relemb, basis, att,
                       node_id, edge_src, edge_typ, rel_idx, out);
    k_div<<<1, 256>>>(out);
}

// round 2
// speedup vs baseline: 2.8699x; 2.8699x over previous
#include <cuda_runtime.h>

// Problem constants (fixed by the reference setup)
#define DE   200          // entity / output dim
#define DR   200          // relation dim
#define DIN  400          // DE + DR
#define NB   4            // num bases

#define MAXM 8192         // matched-edge list capacity (expected ~8)
#define NBLK 148          // <= SM count -> entire grid resident in wave 1
#define NTHR 512

// persistent scratch (static device globals — no allocation).
// Invariant: all of these are back to their initial state (0) at the end of
// every kernel_launch call, so graph replays are deterministic.
__device__ int      g_count;
__device__ int      g_edges[MAXM];
__device__ float    g_acc[DE];
__device__ unsigned g_bar_count[2];
__device__ unsigned g_bar_sense[2];

// Sense-reversing grid barrier. Safe because the grid (NBLK blocks) is fully
// resident. Each barrier id is used exactly once per launch; count self-resets,
// sense monotonically increases (wraps harmlessly).
__device__ __forceinline__ void grid_barrier(int id) {
    __syncthreads();
    if (threadIdx.x == 0) {
        volatile unsigned* sense = &g_bar_sense[id];
        unsigned s = *sense;
        __threadfence();                       // publish this block's writes
        unsigned a = atomicAdd(&g_bar_count[id], 1u);
        if (a == NBLK - 1) {
            g_bar_count[id] = 0;               // reset for next launch
            __threadfence();
            atomicAdd(&g_bar_sense[id], 1u);   // release waiters
        } else {
            while (*sense == s) { __nanosleep(64); }
        }
    }
    __syncthreads();
}

__global__ void __launch_bounds__(NTHR, 1)
fused_kernel(const float* __restrict__ ent,
             const float* __restrict__ relemb,
             const float* __restrict__ basis,
             const float* __restrict__ att,
             const int*   __restrict__ node_id,
             const int*   __restrict__ edge_src,
             const int*   __restrict__ edge_dst,
             const int*   __restrict__ edge_type,
             const int*   __restrict__ rel_index,
             const int*   __restrict__ u_ptr,
             float* __restrict__ out,
             int E) {
    const int tid = threadIdx.x;
    const int gt  = blockIdx.x * NTHR + tid;
    const int GT  = NBLK * NTHR;

    // ── Phase 1: scan edge_dst for matches (vectorized int4) ──
    {
        const int u  = *u_ptr;
        const int nv = E >> 2;
        const int4* ed4 = (const int4*)edge_dst;
        for (int i = gt; i < nv; i += GT) {
            int4 v = ed4[i];
            int base = i << 2;
            if (v.x == u) { int p = atomicAdd(&g_count, 1); if (p < MAXM) g_edges[p] = base + 0; }
            if (v.y == u) { int p = atomicAdd(&g_count, 1); if (p < MAXM) g_edges[p] = base + 1; }
            if (v.z == u) { int p = atomicAdd(&g_count, 1); if (p < MAXM) g_edges[p] = base + 2; }
            if (v.w == u) { int p = atomicAdd(&g_count, 1); if (p < MAXM) g_edges[p] = base + 3; }
        }
        // scalar tail (E not divisible by 4)
        for (int e = (nv << 2) + gt; e < E; e += GT) {
            if (edge_dst[e] == u) { int p = atomicAdd(&g_count, 1); if (p < MAXM) g_edges[p] = e; }
        }
    }

    grid_barrier(0);

    // ── Phase 2: per matched edge, msg = xj @ (sum_b att[t,b] * basis[b]) ──
    {
        int cnt = *(volatile int*)&g_count;
        int mmax = cnt < MAXM ? cnt : MAXM;

        __shared__ float xj[DIN];
        __shared__ float a[NB];

        for (int m = blockIdx.x; m < mmax; m += NBLK) {
            int e   = g_edges[m];
            int nid = node_id[edge_src[e]];
            int ri  = rel_index[e];
            int ty  = edge_type[e];

            if (tid < NB) a[tid] = att[ty * NB + tid];
            for (int i = tid; i < DE; i += NTHR) xj[i]      = ent[(long)nid * DE + i];
            for (int i = tid; i < DR; i += NTHR) xj[DE + i] = relemb[ri * DR + i];
            __syncthreads();

            // split the DIN=400 reduction across two thread halves:
            // threads [0,200) handle i in [0,200); threads [256,456) handle [200,400)
            int half = tid >> 8;          // 0 or 1
            int o    = tid & 255;         // output index within half
            if (o < DE) {
                float a0 = a[0], a1 = a[1], a2 = a[2], a3 = a[3];
                int i0 = half * 200, i1 = i0 + 200;
                float acc = 0.0f;
                #pragma unroll 4
                for (int i = i0; i < i1; i++) {
                    float w = a0 * basis[(0 * DIN + i) * DE + o]
                            + a1 * basis[(1 * DIN + i) * DE + o]
                            + a2 * basis[(2 * DIN + i) * DE + o]
                            + a3 * basis[(3 * DIN + i) * DE + o];
                    acc += xj[i] * w;
                }
                atomicAdd(&g_acc[o], acc);
            }
            __syncthreads();
        }
    }

    grid_barrier(1);

    // ── Phase 3: block 0 normalizes, writes out, resets scratch ──
    if (blockIdx.x == 0) {
        float c   = (float)(*(volatile int*)&g_count);
        float inv = 1.0f / fmaxf(c, 1.0f);
        for (int t = tid; t < DE; t += NTHR) {
            out[t]   = g_acc[t] * inv;
            g_acc[t] = 0.0f;             // reset for next replay
        }
        if (tid == 0) g_count = 0;       // reset for next replay
    }
}

extern "C" void kernel_launch(void* const* d_in, const int* in_sizes, int n_in,
                              void* d_out, int out_size) {
    const float* ent    = (const float*)d_in[0];  // [100000, 200]
    const float* relemb = (const float*)d_in[1];  // [200, 200]
    const float* basis  = (const float*)d_in[2];  // [4, 400, 200]
    const float* att    = (const float*)d_in[3];  // [400, 4]
    const int* node_id  = (const int*)d_in[4];    // [50000]
    const int* edge_src = (const int*)d_in[5];    // [400000]
    const int* edge_dst = (const int*)d_in[6];    // [400000]
    const int* edge_typ = (const int*)d_in[7];    // [400000]
    const int* rel_idx  = (const int*)d_in[8];    // [400000]
    const int* u_ptr    = (const int*)d_in[9];    // scalar
    float* out = (float*)d_out;                   // [200]

    int E = in_sizes[6];

    fused_kernel<<<NBLK, NTHR>>>(ent, relemb, basis, att,
                                 node_id, edge_src, edge_dst, edge_typ, rel_idx,
                                 u_ptr, out, E);
}

// round 3
// speedup vs baseline: 4.2166x; 1.4692x over previous
#include <cuda_runtime.h>

// Problem constants (fixed by the reference setup)
#define DE   200          // entity / output dim
#define DR   200          // relation dim
#define DIN  400          // DE + DR
#define NB   4            // num bases

#define MAXM 8192         // matched-edge list capacity (expected ~8)
#define NBLK 148          // <= SM count -> entire grid resident in wave 1
#define NTHR 512
#define NCH  20           // chunks per edge (DIN/20); chunks 0-9 -> ent, 10-19 -> relemb
#define CHSZ 20           // i-values per chunk

// persistent scratch (static device globals — no allocation).
// Invariant: count/done/acc are back to 0 at the end of every launch so graph
// replays are deterministic. Barrier sense is monotonic (wrap-safe).
__device__ int      g_count;
__device__ int      g_done;
__device__ int      g_edges[MAXM];
__device__ float    g_acc[DE];
__device__ unsigned g_bar_count;
__device__ unsigned g_bar_sense;

// Sense-reversing grid barrier (used once per launch). Grid is fully resident.
__device__ __forceinline__ void grid_barrier() {
    __threadfence();                           // publish every thread's writes
    __syncthreads();
    if (threadIdx.x == 0) {
        volatile unsigned* sense = &g_bar_sense;
        unsigned s = *sense;
        unsigned a = atomicAdd(&g_bar_count, 1u);
        if (a == NBLK - 1) {
            g_bar_count = 0;                   // reset for next launch
            __threadfence();
            atomicAdd(&g_bar_sense, 1u);       // release waiters
        } else {
            while (*sense == s) { }
        }
    }
    __syncthreads();
}

__global__ void __launch_bounds__(NTHR, 1)
fused_kernel(const float* __restrict__ ent,
             const float* __restrict__ relemb,
             const float* __restrict__ basis,
             const float* __restrict__ att,
             const int*   __restrict__ node_id,
             const int*   __restrict__ edge_src,
             const int*   __restrict__ edge_dst,
             const int*   __restrict__ edge_type,
             const int*   __restrict__ rel_index,
             const int*   __restrict__ u_ptr,
             float* __restrict__ out,
             int E) {
    const int tid = threadIdx.x;
    const int gt  = blockIdx.x * NTHR + tid;
    const int GT  = NBLK * NTHR;

    __shared__ float xj[CHSZ];
    __shared__ float a[NB];

    // ── Phase 1: scan edge_dst for matches (vectorized int4) ──
    {
        const int u  = *u_ptr;
        const int nv = E >> 2;
        const int4* ed4 = (const int4*)edge_dst;
        for (int i = gt; i < nv; i += GT) {
            int4 v = ed4[i];
            int base = i << 2;
            if (v.x == u) { int p = atomicAdd(&g_count, 1); if (p < MAXM) g_edges[p] = base + 0; }
            if (v.y == u) { int p = atomicAdd(&g_count, 1); if (p < MAXM) g_edges[p] = base + 1; }
            if (v.z == u) { int p = atomicAdd(&g_count, 1); if (p < MAXM) g_edges[p] = base + 2; }
            if (v.w == u) { int p = atomicAdd(&g_count, 1); if (p < MAXM) g_edges[p] = base + 3; }
        }
        for (int e = (nv << 2) + gt; e < E; e += GT) {     // scalar tail
            if (edge_dst[e] == u) { int p = atomicAdd(&g_count, 1); if (p < MAXM) g_edges[p] = e; }
        }
    }

    grid_barrier();

    // ── Phase 2: work item = (matched edge m, chunk c of the DIN reduction) ──
    // contribution[o] += sum_{i in chunk} xj[i] * (sum_b att[t,b]*basis[b,i,o])
    {
        int cnt  = *(volatile int*)&g_count;
        int mmax = cnt < MAXM ? cnt : MAXM;
        int items = mmax * NCH;

        for (int item = blockIdx.x; item < items; item += NBLK) {
            int m = item / NCH;
            int c = item - m * NCH;
            int e = g_edges[m];
            int i0 = c * CHSZ;

            if (tid < NB) a[tid] = att[edge_type[e] * NB + tid];
            if (tid < CHSZ) {
                int i = i0 + tid;   // chunk is entirely in ent (i<DE) or relemb
                xj[tid] = (i < DE)
                    ? ent[(long)node_id[edge_src[e]] * DE + i]
                    : relemb[rel_index[e] * DR + (i - DE)];
            }
            __syncthreads();

            // threads [0,200): i-subrange [i0, i0+10); threads [256,456): [i0+10, i0+20)
            int half = tid >> 8;
            int o    = tid & 255;
            if (o < DE) {
                float a0 = a[0], a1 = a[1], a2 = a[2], a3 = a[3];
                int ib = i0 + half * (CHSZ / 2);
                float acc = 0.0f;
                #pragma unroll
                for (int j = 0; j < CHSZ / 2; j++) {
                    int i = ib + j;
                    float w = a0 * basis[(0 * DIN + i) * DE + o]
                            + a1 * basis[(1 * DIN + i) * DE + o]
                            + a2 * basis[(2 * DIN + i) * DE + o]
                            + a3 * basis[(3 * DIN + i) * DE + o];
                    acc += xj[half * (CHSZ / 2) + j] * w;
                }
                atomicAdd(&g_acc[o], acc);
            }
            __syncthreads();
        }
    }

    // ── Phase 3: completion counter; block 0 finalizes, others exit ──
    __threadfence();
    __syncthreads();
    if (tid == 0) atomicAdd(&g_done, 1);

    if (blockIdx.x == 0) {
        if (tid == 0) {
            while (*(volatile int*)&g_done != NBLK) { }
            __threadfence();
        }
        __syncthreads();
        float c   = (float)(*(volatile int*)&g_count);
        float inv = 1.0f / fmaxf(c, 1.0f);
        volatile float* acc = g_acc;
        for (int t = tid; t < DE; t += NTHR) {
            out[t]   = acc[t] * inv;
            g_acc[t] = 0.0f;             // reset for next replay
        }
        if (tid == 0) { g_count = 0; g_done = 0; }
    }
}

extern "C" void kernel_launch(void* const* d_in, const int* in_sizes, int n_in,
                              void* d_out, int out_size) {
    const float* ent    = (const float*)d_in[0];  // [100000, 200]
    const float* relemb = (const float*)d_in[1];  // [200, 200]
    const float* basis  = (const float*)d_in[2];  // [4, 400, 200]
    const float* att    = (const float*)d_in[3];  // [400, 4]
    const int* node_id  = (const int*)d_in[4];    // [50000]
    const int* edge_src = (const int*)d_in[5];    // [400000]
    const int* edge_dst = (const int*)d_in[6];    // [400000]
    const int* edge_typ = (const int*)d_in[7];    // [400000]
    const int* rel_idx  = (const int*)d_in[8];    // [400000]
    const int* u_ptr    = (const int*)d_in[9];    // scalar
    float* out = (float*)d_out;                   // [200]

    int E = in_sizes[6];

    fused_kernel<<<NBLK, NTHR>>>(ent, relemb, basis, att,
                                 node_id, edge_src, edge_dst, edge_typ, rel_idx,
                                 u_ptr, out, E);
}

// round 4
// speedup vs baseline: 4.8796x; 1.1572x over previous
#include <cuda_runtime.h>

// Problem constants (fixed by the reference setup)
#define DE   200          // entity / output dim
#define DR   200          // relation dim
#define DIN  400          // DE + DR
#define NB   4            // num bases
#define KTOT (NB * DIN)   // 1600 rows of the collapsed matvec
#define KCH  11           // k-rows per block (148*11 = 1628 >= 1600)

#define MAXM 4096         // matched-edge capacity (expected ~8)
#define NBLK 148          // <= SM count -> whole grid resident in wave 1
#define NTHR 512

// persistent scratch (static device globals — no allocation).
// g_count/g_done/g_acc are reset to 0 at the end of every launch.
__device__ int      g_count;
__device__ int      g_done;
__device__ int      g_nid[MAXM];
__device__ int      g_ri[MAXM];
__device__ float4   g_att[MAXM];
__device__ float    g_acc[DE];
__device__ unsigned g_bar_count;
__device__ unsigned g_bar_sense;

__global__ void __launch_bounds__(NTHR, 1)
fused_kernel(const float* __restrict__ ent,
             const float* __restrict__ relemb,
             const float* __restrict__ basis,
             const float* __restrict__ att,
             const int*   __restrict__ node_id,
             const int*   __restrict__ edge_src,
             const int*   __restrict__ edge_dst,
             const int*   __restrict__ edge_type,
             const int*   __restrict__ rel_index,
             const int*   __restrict__ u_ptr,
             float* __restrict__ out,
             int E) {
    const int tid = threadIdx.x;
    const int gt  = blockIdx.x * NTHR + tid;
    const int GT  = NBLK * NTHR;

    __shared__ float sy[2 * (KCH + 1)]; // y-chunk (12 slots used, padded)

    // ── Phase 1: scan edge_dst; the FINDER resolves the whole pointer chain
    //    (edge_src -> node_id, rel_index, edge_type -> att row) so the 4-deep
    //    dependent latency overlaps with the rest of the scan + barrier. ──
    auto found = [&](int e) {
        int p = atomicAdd(&g_count, 1);
        if (p < MAXM) {
            int s  = __ldcg(&edge_src[e]);
            int ri = __ldcg(&rel_index[e]);
            int ty = __ldcg(&edge_type[e]);
            g_nid[p] = __ldcg(&node_id[s]);
            g_ri[p]  = ri;
            g_att[p] = __ldcg((const float4*)(att + (size_t)ty * NB));
        }
    };
    {
        const int u  = __ldcg(u_ptr);
        const int nv = E >> 2;
        const int4* ed4 = (const int4*)edge_dst;
        for (int i = gt; i < nv; i += GT) {
            int4 v = __ldcg(&ed4[i]);
            int base = i << 2;
            if (v.x == u) found(base + 0);
            if (v.y == u) found(base + 1);
            if (v.z == u) found(base + 2);
            if (v.w == u) found(base + 3);
        }
        for (int e = (nv << 2) + gt; e < E; e += GT) {   // scalar tail
            if (__ldcg(&edge_dst[e]) == u) found(e);
        }
    }

    // ── Grid barrier (CG-style: bar.sync release/acquire + tid0 gpu fence) ──
    __syncthreads();
    if (tid == 0) {
        __threadfence();                       // publish this block's stores
        volatile unsigned* sense = &g_bar_sense;
        unsigned s = *sense;
        unsigned a = atomicAdd(&g_bar_count, 1u);
        if (a == NBLK - 1) {
            g_bar_count = 0;                   // reset for next launch
            __threadfence();
            atomicAdd(&g_bar_sense, 1u);       // release
        } else {
            while (*sense == s) { }
        }
        __threadfence();                       // acquire
    }
    __syncthreads();

    // ── Phase 2: block owns k-rows [k0, k0+kmax) of the collapsed matvec.
    //    y[k] = sum_m att[m][k/DIN] * xj_m[k%DIN];  out[o] += sum_k y[k]*basis[k,o]
    const int cnt  = __ldcg(&g_count);
    const int cntc = cnt < MAXM ? cnt : MAXM;
    const int k0   = blockIdx.x * KCH;
    const int kmax = (KTOT - k0) < KCH ? (KTOT - k0) : KCH;  // may be <= 0

    if (tid < 2 * (KCH + 1)) sy[tid] = 0.0f;
    __syncthreads();

    if (kmax > 0 && cntc > 0) {
        const int total = kmax * cntc;
        for (int p = tid; p < total; p += NTHR) {
            int kk = p / cntc;
            int m  = p - kk * cntc;
            int k  = k0 + kk;
            int b  = k / DIN;
            int i  = k - b * DIN;
            float x = (i < DE)
                ? __ldcg(&ent[(size_t)__ldcg(&g_nid[m]) * DE + i])
                : __ldcg(&relemb[(size_t)__ldcg(&g_ri[m]) * DR + (i - DE)]);
            float a = __ldcg(((const float*)&g_att[m]) + b);
            atomicAdd(&sy[kk], a * x);
        }
    }
    __syncthreads();

    // matvec over this block's k-chunk: group 0 -> kk 0..5, group 1 -> kk 6..10
    {
        int g = tid >> 8;          // 0 or 1
        int o = tid & 255;
        if (kmax > 0 && o < DE) {
            float acc = 0.0f;
            #pragma unroll
            for (int j = 0; j < 6; j++) {
                int kk = g * 6 + j;
                if (kk < kmax)
                    acc += sy[kk] * __ldcg(&basis[(size_t)(k0 + kk) * DE + o]);
            }
            atomicAdd(&g_acc[o], acc);
        }
    }

    // ── Phase 3: completion counter; block 0 finalizes + resets scratch ──
    __syncthreads();
    if (tid == 0) {
        __threadfence();
        atomicAdd(&g_done, 1);
    }
    if (blockIdx.x == 0) {
        if (tid == 0) {
            while (*(volatile int*)&g_done != NBLK) { }
            __threadfence();
        }
        __syncthreads();
        float c   = (float)cnt;
        float inv = 1.0f / fmaxf(c, 1.0f);
        for (int t = tid; t < DE; t += NTHR) {
            out[t]   = __ldcg(&g_acc[t]) * inv;
            g_acc[t] = 0.0f;               // reset for next replay
        }
        if (tid == 0) { g_count = 0; g_done = 0; }
    }
}

extern "C" void kernel_launch(void* const* d_in, const int* in_sizes, int n_in,
                              void* d_out, int out_size) {
    const float* ent    = (const float*)d_in[0];  // [100000, 200]
    const float* relemb = (const float*)d_in[1];  // [200, 200]
    const float* basis  = (const float*)d_in[2];  // [4, 400, 200]
    const float* att    = (const float*)d_in[3];  // [400, 4]
    const int* node_id  = (const int*)d_in[4];    // [50000]
    const int* edge_src = (const int*)d_in[5];    // [400000]
    const int* edge_dst = (const int*)d_in[6];    // [400000]
    const int* edge_typ = (const int*)d_in[7];    // [400000]
    const int* rel_idx  = (const int*)d_in[8];    // [400000]
    const int* u_ptr    = (const int*)d_in[9];    // scalar
    float* out = (float*)d_out;                   // [200]

    int E = in_sizes[6];

    fused_kernel<<<NBLK, NTHR>>>(ent, relemb, basis, att,
                                 node_id, edge_src, edge_dst, edge_typ, rel_idx,
                                 u_ptr, out, E);
}